// round 5
// baseline (speedup 1.0000x reference)
#include <cuda_runtime.h>
#include <cstdint>

// out[s,b,d] = x[s,b,d] + ((S-1)*0.5f - s)
// Pure HBM stream at the measured mixed-stream ceiling (~6.0 TB/s).
// Burst-grouped variant: each thread handles 8 independent 256-bit chunks,
// ALL loads front-batched, then ALL stores — longer same-direction DRAM
// bursts to amortize R/W turnaround.
//
// v8-chunks per s = B*D/8 = 1024 -> s = chunk >> 10.

#define CHUNKS 8

__global__ void __launch_bounds__(256)
relpos_add_kernel(const float* __restrict__ x,
                  float* __restrict__ out,
                  int n8, float half_sm1) {
    int base = (blockIdx.x * blockDim.x) * CHUNKS + threadIdx.x;

    float v[CHUNKS][8];
    int idx[CHUNKS];

    // Phase 1: 8 independent 256-bit loads (2KB read burst per lane)
    #pragma unroll
    for (int k = 0; k < CHUNKS; k++) {
        idx[k] = base + k * blockDim.x;
        if (idx[k] < n8) {
            const float* p = x + (size_t)idx[k] * 8;
            asm volatile("ld.global.cs.v8.f32 {%0,%1,%2,%3,%4,%5,%6,%7}, [%8];"
                         : "=f"(v[k][0]), "=f"(v[k][1]), "=f"(v[k][2]), "=f"(v[k][3]),
                           "=f"(v[k][4]), "=f"(v[k][5]), "=f"(v[k][6]), "=f"(v[k][7])
                         : "l"(p));
        }
    }

    // Phase 2: add bias (tiny FMA work, fully hidden)
    #pragma unroll
    for (int k = 0; k < CHUNKS; k++) {
        float bias = half_sm1 - (float)(idx[k] >> 10);
        #pragma unroll
        for (int j = 0; j < 8; j++) v[k][j] += bias;
    }

    // Phase 3: 8 independent 256-bit stores (2KB write burst per lane)
    #pragma unroll
    for (int k = 0; k < CHUNKS; k++) {
        if (idx[k] < n8) {
            float* p = out + (size_t)idx[k] * 8;
            asm volatile("st.global.cs.v8.f32 [%0], {%1,%2,%3,%4,%5,%6,%7,%8};"
                         :
                         : "l"(p),
                           "f"(v[k][0]), "f"(v[k][1]), "f"(v[k][2]), "f"(v[k][3]),
                           "f"(v[k][4]), "f"(v[k][5]), "f"(v[k][6]), "f"(v[k][7])
                         : "memory");
        }
    }
}

extern "C" void kernel_launch(void* const* d_in, const int* in_sizes, int n_in,
                              void* d_out, int out_size) {
    const float* x = (const float*)d_in[0];
    float* out = (float*)d_out;

    const int total = in_sizes[0];        // 33,554,432
    const int n8 = total / 8;             // 4,194,304
    const int seq_len = total / 8192;     // 4096
    const float half_sm1 = 0.5f * (float)(seq_len - 1);

    const int threads = 256;
    const int per_block = threads * CHUNKS;               // 2048 chunks/block
    const int blocks = (n8 + per_block - 1) / per_block;  // 2048
    relpos_add_kernel<<<blocks, threads>>>(x, out, n8, half_sm1);
}